// round 8
// baseline (speedup 1.0000x reference)
#include <cuda_runtime.h>
#include <cuda_bf16.h>

// ---------------------------------------------------------------------------
// GCN 2-layer forward on GB300.
// CSR pull-aggregation (packed int2 edges) + plain-FFMA tiled GEMM (BK=16).
// Schedule: gemm1 || CSR-build (fork/join), then agg1/gemm2 chunk-pipelined
// across two streams (gemm2 writes h2, NOT h -- avoids WAR race with agg1's
// global gathers of h), then agg2 on h2.
// ---------------------------------------------------------------------------

#define MAX_N 50000
#define MAX_E 800000
#define DIM   128
#define SCAN_B 1024
#define NCHUNK 4

// scratch (device globals -- no allocation allowed)
__device__ int   g_deg  [MAX_N];
__device__ float g_dinv [MAX_N];
__device__ int   g_ptr  [MAX_N + 1];
__device__ int   g_cur  [MAX_N];
__device__ int   g_bsum [64];
__device__ int2  g_cedge[MAX_E];        // {src, float_as_int(norm)}
__device__ float g_h    [MAX_N * DIM];  // gemm1 out
__device__ float g_o1   [MAX_N * DIM];  // agg1 out
__device__ float g_h2   [MAX_N * DIM];  // gemm2 out (separate from g_h!)

// ---------------------------------------------------------------------------
__global__ void k_count(const int* __restrict__ dst, int* deg, int E) {
    int e = blockIdx.x * blockDim.x + threadIdx.x;
    if (e < E) atomicAdd(&deg[dst[e]], 1);
}

// exclusive scan of deg -> ptr (per-block) via shfl; emit block sums; dinv.
__global__ __launch_bounds__(SCAN_B) void k_scan1(const int* __restrict__ deg,
                                                  int* ptr, int* bsum,
                                                  float* dinv, int n) {
    __shared__ int ws[32];
    int t = threadIdx.x;
    int lane = t & 31, w = t >> 5;
    int i = blockIdx.x * SCAN_B + t;
    int v = (i < n) ? deg[i] : 0;
    if (i < n) dinv[i] = rsqrtf((float)(v + 1));

    int x = v;
#pragma unroll
    for (int off = 1; off < 32; off <<= 1) {
        int y = __shfl_up_sync(0xFFFFFFFFu, x, off);
        if (lane >= off) x += y;
    }
    if (lane == 31) ws[w] = x;
    __syncthreads();
    if (w == 0) {
        int s = ws[lane];
#pragma unroll
        for (int off = 1; off < 32; off <<= 1) {
            int y = __shfl_up_sync(0xFFFFFFFFu, s, off);
            if (lane >= off) s += y;
        }
        ws[lane] = s;
    }
    __syncthreads();
    int incl = x + ((w > 0) ? ws[w - 1] : 0);
    if (i < n) ptr[i] = incl - v;                 // exclusive within block
    if (t == SCAN_B - 1) bsum[blockIdx.x] = incl;
}

// add block-prefix -> final ptr, init cur. log-step scan over <=64 block sums.
__global__ void k_scan3(int* ptr, const int* __restrict__ bsum, int* cur,
                        int n, int E, int nb) {
    __shared__ int sb[64];
    int t = threadIdx.x;
    if (t < 64) sb[t] = (t < nb) ? bsum[t] : 0;
    __syncthreads();
#pragma unroll
    for (int off = 1; off < 64; off <<= 1) {
        int x = (t < 64 && t >= off) ? sb[t - off] : 0;
        __syncthreads();
        if (t < 64) sb[t] += x;
        __syncthreads();
    }
    int i = blockIdx.x * blockDim.x + t;
    if (i < n) {
        int blk = i / SCAN_B;
        int pre = (blk > 0) ? sb[blk - 1] : 0;
        int p = ptr[i] + pre;
        ptr[i] = p;
        cur[i] = p;
    }
    if (i == 0) ptr[n] = E;
}

__global__ void k_fill(const int* __restrict__ src, const int* __restrict__ dst,
                       const float* __restrict__ dinv, int* cur,
                       int2* cedge, int E) {
    int e = blockIdx.x * blockDim.x + threadIdx.x;
    if (e >= E) return;
    int s = src[e], d = dst[e];
    int pos = atomicAdd(&cur[d], 1);
    int2 pr;
    pr.x = s;
    pr.y = __float_as_int(dinv[s] * dinv[d]);
    cedge[pos] = pr;
}

// ---------------------------------------------------------------------------
// GEMM: rows [rowoff, rowend) of A@B; BM=128, BK=16, 256 thr, 8x8 microtile.
#define GBM 128
#define GBK 16

template <bool RELU>
__global__ __launch_bounds__(256) void k_gemm(const float* __restrict__ A,
                                              const float* __restrict__ B,
                                              float* __restrict__ C,
                                              int rowoff, int rowend) {
    __shared__ float As[GBK][GBM];   // transposed A tile: As[k][row]
    __shared__ float Bs[GBK][DIM];

    const int tid = threadIdx.x;
    const int m0  = rowoff + blockIdx.x * GBM;
    const int ty  = tid >> 4;   // 0..15 row group
    const int tx  = tid & 15;   // 0..15 col group

    float acc[8][8];
#pragma unroll
    for (int i = 0; i < 8; i++)
#pragma unroll
        for (int j = 0; j < 8; j++) acc[i][j] = 0.0f;

    for (int k0 = 0; k0 < DIM; k0 += GBK) {
        {   // A tile 128x16 -> transposed: two float4 per thread
            int row = tid >> 1;              // 0..127
            int c8  = (tid & 1) * 8;         // 0 or 8
            int gr  = m0 + row;
#pragma unroll
            for (int t = 0; t < 2; t++) {
                float4 v = make_float4(0.f, 0.f, 0.f, 0.f);
                if (gr < rowend)
                    v = *(const float4*)(A + (long)gr * DIM + k0 + c8 + t * 4);
                if (RELU) {
                    v.x = fmaxf(v.x, 0.f); v.y = fmaxf(v.y, 0.f);
                    v.z = fmaxf(v.z, 0.f); v.w = fmaxf(v.w, 0.f);
                }
                As[c8 + t * 4 + 0][row] = v.x;
                As[c8 + t * 4 + 1][row] = v.y;
                As[c8 + t * 4 + 2][row] = v.z;
                As[c8 + t * 4 + 3][row] = v.w;
            }
        }
        {   // B tile 16x128: two float4 per thread
            int r   = tid >> 4;              // 0..15
            int c8  = (tid & 15) * 8;        // 0,8,...,120
#pragma unroll
            for (int t = 0; t < 2; t++)
                *(float4*)(&Bs[r][c8 + t * 4]) =
                    *(const float4*)(B + (long)(k0 + r) * DIM + c8 + t * 4);
        }
        __syncthreads();

#pragma unroll
        for (int k = 0; k < GBK; k++) {
            float a[8], b[8];
            *(float4*)(a)     = *(const float4*)(&As[k][ty * 4]);
            *(float4*)(a + 4) = *(const float4*)(&As[k][ty * 4 + 64]);
            *(float4*)(b)     = *(const float4*)(&Bs[k][tx * 4]);
            *(float4*)(b + 4) = *(const float4*)(&Bs[k][tx * 4 + 64]);
#pragma unroll
            for (int i = 0; i < 8; i++)
#pragma unroll
                for (int j = 0; j < 8; j++)
                    acc[i][j] += a[i] * b[j];
        }
        __syncthreads();
    }

#pragma unroll
    for (int i = 0; i < 8; i++) {
        int gr = m0 + ty * 4 + (i & 3) + (i >> 2) * 64;
        if (gr < rowend) {
            *(float4*)(C + (long)gr * DIM + tx * 4) =
                make_float4(acc[i][0], acc[i][1], acc[i][2], acc[i][3]);
            *(float4*)(C + (long)gr * DIM + tx * 4 + 64) =
                make_float4(acc[i][4], acc[i][5], acc[i][6], acc[i][7]);
        }
    }
}

// ---------------------------------------------------------------------------
// pull-aggregation: warp per node, packed int2 edges; node range [off, end).
__global__ __launch_bounds__(256) void k_agg(const float* __restrict__ h,
                                             const int* __restrict__ ptr,
                                             const int2* __restrict__ cedge,
                                             const float* __restrict__ dinv,
                                             const float* __restrict__ b,
                                             float* __restrict__ out,
                                             int off, int end) {
    int node = off + ((blockIdx.x * blockDim.x + threadIdx.x) >> 5);
    int lane = threadIdx.x & 31;
    if (node >= end) return;

    const float4* h4 = (const float4*)h;
    float di = dinv[node];
    float w0 = di * di;
    float4 hv = h4[(long)node * 32 + lane];
    float4 bv = ((const float4*)b)[lane];
    float4 acc;
    acc.x = hv.x * w0 + bv.x;
    acc.y = hv.y * w0 + bv.y;
    acc.z = hv.z * w0 + bv.z;
    acc.w = hv.w * w0 + bv.w;

    int beg = ptr[node], endp = ptr[node + 1];
    int j = beg;
    for (; j + 3 < endp; j += 4) {
        int2 e0 = cedge[j],     e1 = cedge[j + 1];
        int2 e2 = cedge[j + 2], e3 = cedge[j + 3];
        float n0 = __int_as_float(e0.y), n1 = __int_as_float(e1.y);
        float n2 = __int_as_float(e2.y), n3 = __int_as_float(e3.y);
        float4 v0 = h4[(long)e0.x * 32 + lane];
        float4 v1 = h4[(long)e1.x * 32 + lane];
        float4 v2 = h4[(long)e2.x * 32 + lane];
        float4 v3 = h4[(long)e3.x * 32 + lane];
        acc.x += v0.x * n0; acc.y += v0.y * n0; acc.z += v0.z * n0; acc.w += v0.w * n0;
        acc.x += v1.x * n1; acc.y += v1.y * n1; acc.z += v1.z * n1; acc.w += v1.w * n1;
        acc.x += v2.x * n2; acc.y += v2.y * n2; acc.z += v2.z * n2; acc.w += v2.w * n2;
        acc.x += v3.x * n3; acc.y += v3.y * n3; acc.z += v3.z * n3; acc.w += v3.w * n3;
    }
    for (; j < endp; j++) {
        int2 e = cedge[j];
        float w = __int_as_float(e.y);
        float4 v = h4[(long)e.x * 32 + lane];
        acc.x += v.x * w; acc.y += v.y * w; acc.z += v.z * w; acc.w += v.w * w;
    }
    ((float4*)out)[(long)node * 32 + lane] = acc;
}

// ---------------------------------------------------------------------------
extern "C" void kernel_launch(void* const* d_in, const int* in_sizes, int n_in,
                              void* d_out, int out_size) {
    const float* x  = (const float*)d_in[0];
    const int*   ei = (const int*)  d_in[1];
    const float* W1 = (const float*)d_in[2];
    const float* b1 = (const float*)d_in[3];
    const float* W2 = (const float*)d_in[4];
    const float* b2 = (const float*)d_in[5];
    float* out = (float*)d_out;

    const int N = in_sizes[0] / DIM;
    const int E = in_sizes[1] / 2;
    const int* src = ei;
    const int* dst = ei + E;

    int *deg, *ptr, *cur, *bsum;
    int2* cedge;
    float *dinv, *h, *o1, *h2;
    cudaGetSymbolAddress((void**)&deg,   g_deg);
    cudaGetSymbolAddress((void**)&dinv,  g_dinv);
    cudaGetSymbolAddress((void**)&ptr,   g_ptr);
    cudaGetSymbolAddress((void**)&cur,   g_cur);
    cudaGetSymbolAddress((void**)&bsum,  g_bsum);
    cudaGetSymbolAddress((void**)&cedge, g_cedge);
    cudaGetSymbolAddress((void**)&h,     g_h);
    cudaGetSymbolAddress((void**)&o1,    g_o1);
    cudaGetSymbolAddress((void**)&h2,    g_h2);

    const int T = 256;
    const int nb_scan     = (N + SCAN_B - 1) / SCAN_B;
    const int gemm_blocks = (N + GBM - 1) / GBM;

    // host-side handles only (no device memory)
    cudaStream_t s2;
    cudaStreamCreateWithFlags(&s2, cudaStreamNonBlocking);
    cudaEvent_t e_fork, e_join, e_join2, e_chunk[NCHUNK];
    cudaEventCreateWithFlags(&e_fork,  cudaEventDisableTiming);
    cudaEventCreateWithFlags(&e_join,  cudaEventDisableTiming);
    cudaEventCreateWithFlags(&e_join2, cudaEventDisableTiming);
    for (int c = 0; c < NCHUNK; c++)
        cudaEventCreateWithFlags(&e_chunk[c], cudaEventDisableTiming);

    // ---- fork: GEMM-1 on s2, CSR build on main ----
    cudaEventRecord(e_fork, 0);
    cudaStreamWaitEvent(s2, e_fork, 0);
    k_gemm<false><<<gemm_blocks, 256, 0, s2>>>(x, W1, h, 0, N);
    cudaEventRecord(e_join, s2);

    cudaMemsetAsync(deg, 0, (size_t)N * sizeof(int));
    k_count<<<(E + T - 1) / T, T>>>(dst, deg, E);
    k_scan1<<<nb_scan, SCAN_B>>>(deg, ptr, bsum, dinv, N);
    k_scan3<<<(N + T - 1) / T, T>>>(ptr, bsum, cur, N, E, nb_scan);
    k_fill <<<(E + T - 1) / T, T>>>(src, dst, dinv, cur, cedge, E);

    // ---- agg1 / gemm2 chunk pipeline ----
    // agg1 chunk c: reads h (all rows; gemm1 done), writes o1[c]   (stream 0)
    // gemm2 chunk c: reads o1[c] only, writes h2[c] (fresh buffer) (stream s2)
    cudaStreamWaitEvent(0, e_join, 0);          // agg1 needs h + CSR
    const int chunkN = (N + NCHUNK - 1) / NCHUNK;
    for (int c = 0; c < NCHUNK; c++) {
        int off = c * chunkN;
        int end = min(off + chunkN, N);
        int cnt = end - off;
        if (cnt <= 0) break;
        int ablk = (cnt * 32 + T - 1) / T;
        k_agg<<<ablk, T>>>(h, ptr, cedge, dinv, b1, o1, off, end);
        cudaEventRecord(e_chunk[c], 0);
        cudaStreamWaitEvent(s2, e_chunk[c], 0);
        int gblk = (cnt + GBM - 1) / GBM;
        k_gemm<true><<<gblk, 256, 0, s2>>>(o1, W2, h2, off, end);
    }
    cudaEventRecord(e_join2, s2);

    // ---- agg2 (gathers h2 globally; needs all chunks) ----
    cudaStreamWaitEvent(0, e_join2, 0);
    int ablk_full = (N * 32 + T - 1) / T;
    k_agg<<<ablk_full, T>>>(h2, ptr, cedge, dinv, b2, out, 0, N);
}

// round 12
// speedup vs baseline: 1.0543x; 1.0543x over previous
#include <cuda_runtime.h>
#include <cuda_bf16.h>
#include <cstdint>

// ---------------------------------------------------------------------------
// GCN 2-layer forward on GB300.
// CSR pull-aggregation (packed int2 edges) + warp-level mma.sync bf16-split
// GEMM (A=hi+lo, W=hi+lo; 3 passes HH+HL+LH into fp32 accumulators).
// mma.sync.m16n8k16 is baseline PTX (sm_80+), assembles for sm_103 (non-'a').
// Schedule: [wsplit+gemm1 on s2] || [CSR build on main], join, agg1, gemm2, agg2.
// ---------------------------------------------------------------------------

#define MAX_N 50000
#define MAX_E 800000
#define DIM   128
#define SCAN_B 1024
#define W2STRIDE 65                 // padded row stride in uint32 (bank spread)
#define W2SZ (DIM * W2STRIDE)       // 8320 uint32 per weight image

// scratch (device globals -- no allocation allowed)
__device__ int      g_deg  [MAX_N];
__device__ float    g_dinv [MAX_N];
__device__ int      g_ptr  [MAX_N + 1];
__device__ int      g_cur  [MAX_N];
__device__ int      g_bsum [64];
__device__ int2     g_cedge[MAX_E];
__device__ float    g_h    [MAX_N * DIM];
__device__ float    g_o1   [MAX_N * DIM];
__device__ float    g_h2   [MAX_N * DIM];
// pre-split, transposed, pair-packed weights: Wt2[n][k/2], uint32={bf16(k),bf16(k+1)}
__device__ uint32_t g_w1h[W2SZ];
__device__ uint32_t g_w1l[W2SZ];
__device__ uint32_t g_w2h[W2SZ];
__device__ uint32_t g_w2l[W2SZ];

// ---------------------------------------------------------------------------
__device__ __forceinline__ void bf16_split(float f, unsigned short& hi, unsigned short& lo) {
    __nv_bfloat16 h = __float2bfloat16(f);
    float fh = __bfloat162float(h);
    __nv_bfloat16 l = __float2bfloat16(f - fh);
    hi = __bfloat16_as_ushort(h);
    lo = __bfloat16_as_ushort(l);
}
__device__ __forceinline__ uint32_t pack2(unsigned short even_k, unsigned short odd_k) {
    return (uint32_t)even_k | ((uint32_t)odd_k << 16);
}

__device__ __forceinline__ void mma16816(float* d, const uint32_t* a,
                                         uint32_t b0, uint32_t b1) {
    asm volatile(
        "mma.sync.aligned.m16n8k16.row.col.f32.bf16.bf16.f32 "
        "{%0,%1,%2,%3}, {%4,%5,%6,%7}, {%8,%9}, {%0,%1,%2,%3};"
        : "+f"(d[0]), "+f"(d[1]), "+f"(d[2]), "+f"(d[3])
        : "r"(a[0]), "r"(a[1]), "r"(a[2]), "r"(a[3]), "r"(b0), "r"(b1));
}

// ---------------------------------------------------------------------------
// weight prep: W[k][n] f32 -> Wt2h/Wt2l[n][k2] packed bf16 pairs (split).
__global__ void k_wsplit(const float* __restrict__ W,
                         uint32_t* __restrict__ Wh,
                         uint32_t* __restrict__ Wl) {
    int i = blockIdx.x * blockDim.x + threadIdx.x;
    if (i >= DIM * (DIM / 2)) return;
    int n = i >> 6, k2 = i & 63;
    float w0 = W[(2 * k2)     * DIM + n];
    float w1 = W[(2 * k2 + 1) * DIM + n];
    unsigned short h0, l0, h1, l1;
    bf16_split(w0, h0, l0);
    bf16_split(w1, h1, l1);
    Wh[n * W2STRIDE + k2] = pack2(h0, h1);
    Wl[n * W2STRIDE + k2] = pack2(l0, l1);
}

// ---------------------------------------------------------------------------
// GEMM via mma.sync: C[128-tile,128] = A@W, bf16-split 3-pass.
// 256 thr = 8 warps in 4x2; warp tile m32 x n64.
#define SMA_H 0
#define SMA_L (SMA_H + W2SZ)
#define SMB_H (SMA_L + W2SZ)
#define SMB_L (SMB_H + W2SZ)
#define SM_U32 (4 * W2SZ)                   // 33280 uint32 = 133120 B

template <bool RELU>
__global__ __launch_bounds__(256) void k_gemm_mma(const float* __restrict__ A,
                                                  const uint32_t* __restrict__ Bh,
                                                  const uint32_t* __restrict__ Bl,
                                                  float* __restrict__ C, int M) {
    extern __shared__ uint32_t sm[];
    const int tid  = threadIdx.x;
    const int m0   = blockIdx.x * 128;
    const int w    = tid >> 5;
    const int lane = tid & 31;
    const int g    = lane >> 2;     // 0..7
    const int t4   = lane & 3;      // 0..3
    const int wm   = w & 3;         // 4 row-blocks of 32
    const int wn   = w >> 2;        // 2 col-blocks of 64

    // --- stage B (pre-packed) ---
    for (int i = tid; i < W2SZ; i += 256) {
        sm[SMB_H + i] = Bh[i];
        sm[SMB_L + i] = Bl[i];
    }
    // --- stage A: load f32, (relu), split, pack pairs along k ---
    for (int i = tid; i < 128 * 32; i += 256) {
        int row = i >> 5, c4 = i & 31;
        int gr = m0 + row;
        float4 v = make_float4(0.f, 0.f, 0.f, 0.f);
        if (gr < M) v = *(const float4*)(A + (long)gr * DIM + c4 * 4);
        if (RELU) {
            v.x = fmaxf(v.x, 0.f); v.y = fmaxf(v.y, 0.f);
            v.z = fmaxf(v.z, 0.f); v.w = fmaxf(v.w, 0.f);
        }
        unsigned short hx, lx, hy, ly, hz, lz, hw, lw;
        bf16_split(v.x, hx, lx); bf16_split(v.y, hy, ly);
        bf16_split(v.z, hz, lz); bf16_split(v.w, hw, lw);
        int base = row * W2STRIDE + c4 * 2;
        sm[SMA_H + base]     = pack2(hx, hy);
        sm[SMA_H + base + 1] = pack2(hz, hw);
        sm[SMA_L + base]     = pack2(lx, ly);
        sm[SMA_L + base + 1] = pack2(lz, lw);
    }
    __syncthreads();

    float acc[2][8][4];
#pragma unroll
    for (int mt = 0; mt < 2; mt++)
#pragma unroll
        for (int nt = 0; nt < 8; nt++)
#pragma unroll
            for (int q = 0; q < 4; q++) acc[mt][nt][q] = 0.f;

#pragma unroll
    for (int ks = 0; ks < 8; ks++) {
        const int kb = ks * 8;
        uint32_t ah[2][4], al[2][4];
#pragma unroll
        for (int mt = 0; mt < 2; mt++) {
            int r  = wm * 32 + mt * 16 + g;
            int i0 = r * W2STRIDE + kb + t4;
            int i1 = (r + 8) * W2STRIDE + kb + t4;
            ah[mt][0] = sm[SMA_H + i0];     ah[mt][1] = sm[SMA_H + i1];
            ah[mt][2] = sm[SMA_H + i0 + 4]; ah[mt][3] = sm[SMA_H + i1 + 4];
            al[mt][0] = sm[SMA_L + i0];     al[mt][1] = sm[SMA_L + i1];
            al[mt][2] = sm[SMA_L + i0 + 4]; al[mt][3] = sm[SMA_L + i1 + 4];
        }
#pragma unroll
        for (int nt = 0; nt < 8; nt++) {
            int n  = wn * 64 + nt * 8 + g;
            int bi = n * W2STRIDE + kb + t4;
            uint32_t bh0 = sm[SMB_H + bi], bh1 = sm[SMB_H + bi + 4];
            uint32_t bl0 = sm[SMB_L + bi], bl1 = sm[SMB_L + bi + 4];
#pragma unroll
            for (int mt = 0; mt < 2; mt++) {
                mma16816(acc[mt][nt], ah[mt], bh0, bh1);   // HH
                mma16816(acc[mt][nt], ah[mt], bl0, bl1);   // HL
                mma16816(acc[mt][nt], al[mt], bh0, bh1);   // LH
            }
        }
    }

    // epilogue: d0=[g][2t4], d1=[g][2t4+1], d2=[g+8][2t4], d3=[g+8][2t4+1]
#pragma unroll
    for (int mt = 0; mt < 2; mt++) {
        int r0 = m0 + wm * 32 + mt * 16 + g;
        int r1 = r0 + 8;
#pragma unroll
        for (int nt = 0; nt < 8; nt++) {
            int col = wn * 64 + nt * 8 + 2 * t4;
            if (r0 < M)
                *(float2*)(C + (long)r0 * DIM + col) =
                    make_float2(acc[mt][nt][0], acc[mt][nt][1]);
            if (r1 < M)
                *(float2*)(C + (long)r1 * DIM + col) =
                    make_float2(acc[mt][nt][2], acc[mt][nt][3]);
        }
    }
}

// ---------------------------------------------------------------------------
// CSR build (ILP-4 count/fill)
__global__ void k_count(const int* __restrict__ dst, int* deg, int E) {
    int base = (blockIdx.x * blockDim.x + threadIdx.x) * 4;
    if (base + 3 < E) {
        int4 d4 = *(const int4*)(dst + base);
        atomicAdd(&deg[d4.x], 1);
        atomicAdd(&deg[d4.y], 1);
        atomicAdd(&deg[d4.z], 1);
        atomicAdd(&deg[d4.w], 1);
    } else {
        for (int e = base; e < E; e++) atomicAdd(&deg[dst[e]], 1);
    }
}

__global__ __launch_bounds__(SCAN_B) void k_scan1(const int* __restrict__ deg,
                                                  int* ptr, int* bsum,
                                                  float* dinv, int n) {
    __shared__ int ws[32];
    int t = threadIdx.x;
    int lane = t & 31, w = t >> 5;
    int i = blockIdx.x * SCAN_B + t;
    int v = (i < n) ? deg[i] : 0;
    if (i < n) dinv[i] = rsqrtf((float)(v + 1));
    int x = v;
#pragma unroll
    for (int off = 1; off < 32; off <<= 1) {
        int y = __shfl_up_sync(0xFFFFFFFFu, x, off);
        if (lane >= off) x += y;
    }
    if (lane == 31) ws[w] = x;
    __syncthreads();
    if (w == 0) {
        int s = ws[lane];
#pragma unroll
        for (int off = 1; off < 32; off <<= 1) {
            int y = __shfl_up_sync(0xFFFFFFFFu, s, off);
            if (lane >= off) s += y;
        }
        ws[lane] = s;
    }
    __syncthreads();
    int incl = x + ((w > 0) ? ws[w - 1] : 0);
    if (i < n) ptr[i] = incl - v;
    if (t == SCAN_B - 1) bsum[blockIdx.x] = incl;
}

__global__ void k_scan3(int* ptr, const int* __restrict__ bsum, int* cur,
                        int n, int E, int nb) {
    __shared__ int sb_[64];
    int t = threadIdx.x;
    if (t < 64) sb_[t] = (t < nb) ? bsum[t] : 0;
    __syncthreads();
#pragma unroll
    for (int off = 1; off < 64; off <<= 1) {
        int x = (t < 64 && t >= off) ? sb_[t - off] : 0;
        __syncthreads();
        if (t < 64) sb_[t] += x;
        __syncthreads();
    }
    int i = blockIdx.x * blockDim.x + t;
    if (i < n) {
        int blk = i / SCAN_B;
        int pre = (blk > 0) ? sb_[blk - 1] : 0;
        int p = ptr[i] + pre;
        ptr[i] = p;
        cur[i] = p;
    }
    if (i == 0) ptr[n] = E;
}

__global__ void k_fill(const int* __restrict__ src, const int* __restrict__ dst,
                       const float* __restrict__ dinv, int* cur,
                       int2* cedge, int E) {
    int base = (blockIdx.x * blockDim.x + threadIdx.x) * 4;
    if (base + 3 < E) {
        int4 s4 = *(const int4*)(src + base);
        int4 d4 = *(const int4*)(dst + base);
        float ns0 = dinv[s4.x], ns1 = dinv[s4.y], ns2 = dinv[s4.z], ns3 = dinv[s4.w];
        float nd0 = dinv[d4.x], nd1 = dinv[d4.y], nd2 = dinv[d4.z], nd3 = dinv[d4.w];
        int p0 = atomicAdd(&cur[d4.x], 1);
        int p1 = atomicAdd(&cur[d4.y], 1);
        int p2 = atomicAdd(&cur[d4.z], 1);
        int p3 = atomicAdd(&cur[d4.w], 1);
        cedge[p0] = make_int2(s4.x, __float_as_int(ns0 * nd0));
        cedge[p1] = make_int2(s4.y, __float_as_int(ns1 * nd1));
        cedge[p2] = make_int2(s4.z, __float_as_int(ns2 * nd2));
        cedge[p3] = make_int2(s4.w, __float_as_int(ns3 * nd3));
    } else {
        for (int e = base; e < E; e++) {
            int s = src[e], d = dst[e];
            int pos = atomicAdd(&cur[d], 1);
            cedge[pos] = make_int2(s, __float_as_int(dinv[s] * dinv[d]));
        }
    }
}

// ---------------------------------------------------------------------------
// pull-aggregation: warp per node, packed int2 edges.
__global__ __launch_bounds__(256) void k_agg(const float* __restrict__ h,
                                             const int* __restrict__ ptr,
                                             const int2* __restrict__ cedge,
                                             const float* __restrict__ dinv,
                                             const float* __restrict__ b,
                                             float* __restrict__ out, int n) {
    int node = (blockIdx.x * blockDim.x + threadIdx.x) >> 5;
    int lane = threadIdx.x & 31;
    if (node >= n) return;

    const float4* h4 = (const float4*)h;
    float di = dinv[node];
    float w0 = di * di;
    float4 hv = h4[(long)node * 32 + lane];
    float4 bv = ((const float4*)b)[lane];
    float4 acc;
    acc.x = hv.x * w0 + bv.x;
    acc.y = hv.y * w0 + bv.y;
    acc.z = hv.z * w0 + bv.z;
    acc.w = hv.w * w0 + bv.w;

    int beg = ptr[node], endp = ptr[node + 1];
    int j = beg;
    for (; j + 3 < endp; j += 4) {
        int2 e0 = cedge[j],     e1 = cedge[j + 1];
        int2 e2 = cedge[j + 2], e3 = cedge[j + 3];
        float n0 = __int_as_float(e0.y), n1 = __int_as_float(e1.y);
        float n2 = __int_as_float(e2.y), n3 = __int_as_float(e3.y);
        float4 v0 = h4[(long)e0.x * 32 + lane];
        float4 v1 = h4[(long)e1.x * 32 + lane];
        float4 v2 = h4[(long)e2.x * 32 + lane];
        float4 v3 = h4[(long)e3.x * 32 + lane];
        acc.x += v0.x * n0; acc.y += v0.y * n0; acc.z += v0.z * n0; acc.w += v0.w * n0;
        acc.x += v1.x * n1; acc.y += v1.y * n1; acc.z += v1.z * n1; acc.w += v1.w * n1;
        acc.x += v2.x * n2; acc.y += v2.y * n2; acc.z += v2.z * n2; acc.w += v2.w * n2;
        acc.x += v3.x * n3; acc.y += v3.y * n3; acc.z += v3.z * n3; acc.w += v3.w * n3;
    }
    for (; j < endp; j++) {
        int2 e = cedge[j];
        float w = __int_as_float(e.y);
        float4 v = h4[(long)e.x * 32 + lane];
        acc.x += v.x * w; acc.y += v.y * w; acc.z += v.z * w; acc.w += v.w * w;
    }
    ((float4*)out)[(long)node * 32 + lane] = acc;
}

// ---------------------------------------------------------------------------
extern "C" void kernel_launch(void* const* d_in, const int* in_sizes, int n_in,
                              void* d_out, int out_size) {
    const float* x  = (const float*)d_in[0];
    const int*   ei = (const int*)  d_in[1];
    const float* W1 = (const float*)d_in[2];
    const float* b1 = (const float*)d_in[3];
    const float* W2 = (const float*)d_in[4];
    const float* b2 = (const float*)d_in[5];
    float* out = (float*)d_out;

    const int N = in_sizes[0] / DIM;
    const int E = in_sizes[1] / 2;
    const int* src = ei;
    const int* dst = ei + E;

    int *deg, *ptr, *cur, *bsum;
    int2* cedge;
    float *dinv, *h, *o1, *h2;
    uint32_t *w1h, *w1l, *w2h, *w2l;
    cudaGetSymbolAddress((void**)&deg,   g_deg);
    cudaGetSymbolAddress((void**)&dinv,  g_dinv);
    cudaGetSymbolAddress((void**)&ptr,   g_ptr);
    cudaGetSymbolAddress((void**)&cur,   g_cur);
    cudaGetSymbolAddress((void**)&bsum,  g_bsum);
    cudaGetSymbolAddress((void**)&cedge, g_cedge);
    cudaGetSymbolAddress((void**)&h,     g_h);
    cudaGetSymbolAddress((void**)&o1,    g_o1);
    cudaGetSymbolAddress((void**)&h2,    g_h2);
    cudaGetSymbolAddress((void**)&w1h,   g_w1h);
    cudaGetSymbolAddress((void**)&w1l,   g_w1l);
    cudaGetSymbolAddress((void**)&w2h,   g_w2h);
    cudaGetSymbolAddress((void**)&w2l,   g_w2l);

    const size_t smem_bytes = SM_U32 * sizeof(uint32_t);
    cudaFuncSetAttribute(k_gemm_mma<false>,
                         cudaFuncAttributeMaxDynamicSharedMemorySize, (int)smem_bytes);
    cudaFuncSetAttribute(k_gemm_mma<true>,
                         cudaFuncAttributeMaxDynamicSharedMemorySize, (int)smem_bytes);

    const int T = 256;
    const int nb_scan     = (N + SCAN_B - 1) / SCAN_B;
    const int gemm_blocks = (N + 127) / 128;

    cudaStream_t s2;
    cudaStreamCreateWithFlags(&s2, cudaStreamNonBlocking);
    cudaEvent_t e_fork, e_join;
    cudaEventCreateWithFlags(&e_fork, cudaEventDisableTiming);
    cudaEventCreateWithFlags(&e_join, cudaEventDisableTiming);

    // ---- fork: weight split + GEMM-1 on s2, CSR build on main ----
    cudaEventRecord(e_fork, 0);
    cudaStreamWaitEvent(s2, e_fork, 0);
    k_wsplit<<<(DIM * DIM / 2 + T - 1) / T, T, 0, s2>>>(W1, w1h, w1l);
    k_wsplit<<<(DIM * DIM / 2 + T - 1) / T, T, 0, s2>>>(W2, w2h, w2l);
    k_gemm_mma<false><<<gemm_blocks, 256, smem_bytes, s2>>>(x, w1h, w1l, h, N);
    cudaEventRecord(e_join, s2);

    cudaMemsetAsync(deg, 0, (size_t)N * sizeof(int));
    k_count<<<(E / 4 + T - 1) / T, T>>>(dst, deg, E);
    k_scan1<<<nb_scan, SCAN_B>>>(deg, ptr, bsum, dinv, N);
    k_scan3<<<(N + T - 1) / T, T>>>(ptr, bsum, cur, N, E, nb_scan);
    k_fill <<<(E / 4 + T - 1) / T, T>>>(src, dst, dinv, cur, cedge, E);

    // ---- join, then serial layer pipeline ----
    cudaStreamWaitEvent(0, e_join, 0);
    int ablk = (N * 32 + T - 1) / T;
    k_agg<<<ablk, T>>>(h, ptr, cedge, dinv, b1, o1, N);
    k_gemm_mma<true><<<gemm_blocks, 256, smem_bytes>>>(o1, w2h, w2l, h2, N);
    k_agg<<<ablk, T>>>(h2, ptr, cedge, dinv, b2, out, N);
}

// round 13
// speedup vs baseline: 1.1325x; 1.0742x over previous
#include <cuda_runtime.h>
#include <cuda_bf16.h>
#include <cstdint>

// ---------------------------------------------------------------------------
// GCN 2-layer forward on GB300.
// CSR pull-aggregation (packed int2 edges) + mma.sync bf16-split GEMM
// (3 passes HH+HL+LH, fp32 accum) with CONFLICT-FREE smem layout:
// k-pair-major, stride 68 u32 (== 4 mod 32)  ->  bank = 4g + t4, all distinct.
// Schedule: [wsplit x2 + gemm1 on s2] || [CSR build on main]; join; serial
// agg1 -> gemm2 -> agg2.
// ---------------------------------------------------------------------------

#define MAX_N 50000
#define MAX_E 800000
#define DIM   128
#define SCAN_B 1024
#define AST 68                       // row stride in u32 for A/B images (4 mod 32)
#define WIMG (DIM * AST)             // 8704 u32 per weight image

// scratch (device globals -- no allocation allowed)
__device__ int      g_deg  [MAX_N];
__device__ float    g_dinv [MAX_N];
__device__ int      g_ptr  [MAX_N + 1];
__device__ int      g_cur  [MAX_N];
__device__ int      g_bsum [64];
__device__ int2     g_cedge[MAX_E];
__device__ float    g_h    [MAX_N * DIM];
__device__ float    g_o1   [MAX_N * DIM];
__device__ float    g_h2   [MAX_N * DIM];
// pre-split, transposed, pair-packed weights: W[n][k2] u32 = {bf16(2k2),bf16(2k2+1)}
__device__ uint32_t g_w1h[WIMG];
__device__ uint32_t g_w1l[WIMG];
__device__ uint32_t g_w2h[WIMG];
__device__ uint32_t g_w2l[WIMG];

// ---------------------------------------------------------------------------
__device__ __forceinline__ void bf16_split(float f, unsigned short& hi, unsigned short& lo) {
    __nv_bfloat16 h = __float2bfloat16(f);
    float fh = __bfloat162float(h);
    __nv_bfloat16 l = __float2bfloat16(f - fh);
    hi = __bfloat16_as_ushort(h);
    lo = __bfloat16_as_ushort(l);
}
__device__ __forceinline__ uint32_t pack2(unsigned short even_k, unsigned short odd_k) {
    return (uint32_t)even_k | ((uint32_t)odd_k << 16);
}
__device__ __forceinline__ void mma16816(float* d, const uint32_t* a,
                                         uint32_t b0, uint32_t b1) {
    asm volatile(
        "mma.sync.aligned.m16n8k16.row.col.f32.bf16.bf16.f32 "
        "{%0,%1,%2,%3}, {%4,%5,%6,%7}, {%8,%9}, {%0,%1,%2,%3};"
        : "+f"(d[0]), "+f"(d[1]), "+f"(d[2]), "+f"(d[3])
        : "r"(a[0]), "r"(a[1]), "r"(a[2]), "r"(a[3]), "r"(b0), "r"(b1));
}

// ---------------------------------------------------------------------------
// weight prep: W[k][n] f32 -> per-image [n][k2] packed bf16 pairs, stride AST.
__global__ void k_wsplit(const float* __restrict__ W,
                         uint32_t* __restrict__ Wh,
                         uint32_t* __restrict__ Wl) {
    int i = blockIdx.x * blockDim.x + threadIdx.x;
    if (i >= DIM * (DIM / 2)) return;
    int n = i >> 6, k2 = i & 63;
    float w0 = W[(2 * k2)     * DIM + n];
    float w1 = W[(2 * k2 + 1) * DIM + n];
    unsigned short h0, l0, h1, l1;
    bf16_split(w0, h0, l0);
    bf16_split(w1, h1, l1);
    Wh[n * AST + k2] = pack2(h0, h1);
    Wl[n * AST + k2] = pack2(l0, l1);
}

// ---------------------------------------------------------------------------
// GEMM via mma.sync: C[128-tile,128] = A@W, bf16-split 3-pass.
// 256 thr = 8 warps in 4x2; warp tile m32 x n64. All smem images [row][k2],
// stride AST=68 -> inner-loop LDS bank = (4g + t4) mod 32: conflict-free.
#define SMA_H 0
#define SMA_L (SMA_H + WIMG)
#define SMB_H (SMA_L + WIMG)
#define SMB_L (SMB_H + WIMG)
#define SM_U32 (4 * WIMG)            // 34816 u32 = 139264 B

template <bool RELU>
__global__ __launch_bounds__(256) void k_gemm_mma(const float* __restrict__ A,
                                                  const uint32_t* __restrict__ Bh,
                                                  const uint32_t* __restrict__ Bl,
                                                  float* __restrict__ C, int M) {
    extern __shared__ uint32_t sm[];
    const int tid  = threadIdx.x;
    const int m0   = blockIdx.x * 128;
    const int w    = tid >> 5;
    const int lane = tid & 31;
    const int g    = lane >> 2;     // 0..7
    const int t4   = lane & 3;      // 0..3
    const int wm   = w & 3;         // 4 row-blocks of 32
    const int wn   = w >> 2;        // 2 col-blocks of 64

    // --- stage B (pre-packed, stride AST): linear float4 copy ---
    for (int i = tid; i < WIMG / 4; i += 256) {
        ((float4*)(sm + SMB_H))[i] = ((const float4*)Bh)[i];
        ((float4*)(sm + SMB_L))[i] = ((const float4*)Bl)[i];
    }
    // --- stage A: coalesced f32 load, (relu), split, paired STS.64 ---
    for (int i = tid; i < 128 * 32; i += 256) {
        int row = i >> 5, c4 = i & 31;
        int gr = m0 + row;
        float4 v = make_float4(0.f, 0.f, 0.f, 0.f);
        if (gr < M) v = *(const float4*)(A + (long)gr * DIM + c4 * 4);
        if (RELU) {
            v.x = fmaxf(v.x, 0.f); v.y = fmaxf(v.y, 0.f);
            v.z = fmaxf(v.z, 0.f); v.w = fmaxf(v.w, 0.f);
        }
        unsigned short hx, lx, hy, ly, hz, lz, hw, lw;
        bf16_split(v.x, hx, lx); bf16_split(v.y, hy, ly);
        bf16_split(v.z, hz, lz); bf16_split(v.w, hw, lw);
        int base = row * AST + 2 * c4;           // even -> 8B aligned
        *(uint2*)(sm + SMA_H + base) = make_uint2(pack2(hx, hy), pack2(hz, hw));
        *(uint2*)(sm + SMA_L + base) = make_uint2(pack2(lx, ly), pack2(lz, lw));
    }
    __syncthreads();

    float acc[2][8][4];
#pragma unroll
    for (int mt = 0; mt < 2; mt++)
#pragma unroll
        for (int nt = 0; nt < 8; nt++)
#pragma unroll
            for (int q = 0; q < 4; q++) acc[mt][nt][q] = 0.f;

#pragma unroll
    for (int ks = 0; ks < 8; ks++) {
        const int kb = ks * 8;
        uint32_t ah[2][4], al[2][4];
#pragma unroll
        for (int mt = 0; mt < 2; mt++) {
            int r  = wm * 32 + mt * 16 + g;
            int i0 = r * AST + kb + t4;          // bank 4g+t4 : conflict-free
            int i1 = i0 + 8 * AST;               // row + 8
            ah[mt][0] = sm[SMA_H + i0];     ah[mt][1] = sm[SMA_H + i1];
            ah[mt][2] = sm[SMA_H + i0 + 4]; ah[mt][3] = sm[SMA_H + i1 + 4];
            al[mt][0] = sm[SMA_L + i0];     al[mt][1] = sm[SMA_L + i1];
            al[mt][2] = sm[SMA_L + i0 + 4]; al[mt][3] = sm[SMA_L + i1 + 4];
        }
#pragma unroll
        for (int nt = 0; nt < 8; nt++) {
            int n  = wn * 64 + nt * 8 + g;
            int bi = n * AST + kb + t4;          // bank 4g+t4 : conflict-free
            uint32_t bh0 = sm[SMB_H + bi], bh1 = sm[SMB_H + bi + 4];
            uint32_t bl0 = sm[SMB_L + bi], bl1 = sm[SMB_L + bi + 4];
#pragma unroll
            for (int mt = 0; mt < 2; mt++) {
                mma16816(acc[mt][nt], ah[mt], bh0, bh1);   // HH
                mma16816(acc[mt][nt], ah[mt], bl0, bl1);   // HL
                mma16816(acc[mt][nt], al[mt], bh0, bh1);   // LH
            }
        }
    }

    // epilogue
#pragma unroll
    for (int mt = 0; mt < 2; mt++) {
        int r0 = m0 + wm * 32 + mt * 16 + g;
        int r1 = r0 + 8;
#pragma unroll
        for (int nt = 0; nt < 8; nt++) {
            int col = wn * 64 + nt * 8 + 2 * t4;
            if (r0 < M)
                *(float2*)(C + (long)r0 * DIM + col) =
                    make_float2(acc[mt][nt][0], acc[mt][nt][1]);
            if (r1 < M)
                *(float2*)(C + (long)r1 * DIM + col) =
                    make_float2(acc[mt][nt][2], acc[mt][nt][3]);
        }
    }
}

// ---------------------------------------------------------------------------
// CSR build (ILP-4 count/fill)
__global__ void k_count(const int* __restrict__ dst, int* deg, int E) {
    int base = (blockIdx.x * blockDim.x + threadIdx.x) * 4;
    if (base + 3 < E) {
        int4 d4 = *(const int4*)(dst + base);
        atomicAdd(&deg[d4.x], 1);
        atomicAdd(&deg[d4.y], 1);
        atomicAdd(&deg[d4.z], 1);
        atomicAdd(&deg[d4.w], 1);
    } else {
        for (int e = base; e < E; e++) atomicAdd(&deg[dst[e]], 1);
    }
}

__global__ __launch_bounds__(SCAN_B) void k_scan1(const int* __restrict__ deg,
                                                  int* ptr, int* bsum,
                                                  float* dinv, int n) {
    __shared__ int ws[32];
    int t = threadIdx.x;
    int lane = t & 31, w = t >> 5;
    int i = blockIdx.x * SCAN_B + t;
    int v = (i < n) ? deg[i] : 0;
    if (i < n) dinv[i] = rsqrtf((float)(v + 1));
    int x = v;
#pragma unroll
    for (int off = 1; off < 32; off <<= 1) {
        int y = __shfl_up_sync(0xFFFFFFFFu, x, off);
        if (lane >= off) x += y;
    }
    if (lane == 31) ws[w] = x;
    __syncthreads();
    if (w == 0) {
        int s = ws[lane];
#pragma unroll
        for (int off = 1; off < 32; off <<= 1) {
            int y = __shfl_up_sync(0xFFFFFFFFu, s, off);
            if (lane >= off) s += y;
        }
        ws[lane] = s;
    }
    __syncthreads();
    int incl = x + ((w > 0) ? ws[w - 1] : 0);
    if (i < n) ptr[i] = incl - v;
    if (t == SCAN_B - 1) bsum[blockIdx.x] = incl;
}

__global__ void k_scan3(int* ptr, const int* __restrict__ bsum, int* cur,
                        int n, int E, int nb) {
    __shared__ int sb_[64];
    int t = threadIdx.x;
    if (t < 64) sb_[t] = (t < nb) ? bsum[t] : 0;
    __syncthreads();
#pragma unroll
    for (int off = 1; off < 64; off <<= 1) {
        int x = (t < 64 && t >= off) ? sb_[t - off] : 0;
        __syncthreads();
        if (t < 64) sb_[t] += x;
        __syncthreads();
    }
    int i = blockIdx.x * blockDim.x + t;
    if (i < n) {
        int blk = i / SCAN_B;
        int pre = (blk > 0) ? sb_[blk - 1] : 0;
        int p = ptr[i] + pre;
        ptr[i] = p;
        cur[i] = p;
    }
    if (i == 0) ptr[n] = E;
}

__global__ void k_fill(const int* __restrict__ src, const int* __restrict__ dst,
                       const float* __restrict__ dinv, int* cur,
                       int2* cedge, int E) {
    int base = (blockIdx.x * blockDim.x + threadIdx.x) * 4;
    if (base + 3 < E) {
        int4 s4 = *(const int4*)(src + base);
        int4 d4 = *(const int4*)(dst + base);
        float ns0 = dinv[s4.x], ns1 = dinv[s4.y], ns2 = dinv[s4.z], ns3 = dinv[s4.w];
        float nd0 = dinv[d4.x], nd1 = dinv[d4.y], nd2 = dinv[d4.z], nd3 = dinv[d4.w];
        int p0 = atomicAdd(&cur[d4.x], 1);
        int p1 = atomicAdd(&cur[d4.y], 1);
        int p2 = atomicAdd(&cur[d4.z], 1);
        int p3 = atomicAdd(&cur[d4.w], 1);
        cedge[p0] = make_int2(s4.x, __float_as_int(ns0 * nd0));
        cedge[p1] = make_int2(s4.y, __float_as_int(ns1 * nd1));
        cedge[p2] = make_int2(s4.z, __float_as_int(ns2 * nd2));
        cedge[p3] = make_int2(s4.w, __float_as_int(ns3 * nd3));
    } else {
        for (int e = base; e < E; e++) {
            int s = src[e], d = dst[e];
            int pos = atomicAdd(&cur[d], 1);
            cedge[pos] = make_int2(s, __float_as_int(dinv[s] * dinv[d]));
        }
    }
}

// ---------------------------------------------------------------------------
// pull-aggregation: warp per node, packed int2 edges.
__global__ __launch_bounds__(256) void k_agg(const float* __restrict__ h,
                                             const int* __restrict__ ptr,
                                             const int2* __restrict__ cedge,
                                             const float* __restrict__ dinv,
                                             const float* __restrict__ b,
                                             float* __restrict__ out, int n) {
    int node = (blockIdx.x * blockDim.x + threadIdx.x) >> 5;
    int lane = threadIdx.x & 31;
    if (node >= n) return;

    const float4* h4 = (const float4*)h;
    float di = dinv[node];
    float w0 = di * di;
    float4 hv = h4[(long)node * 32 + lane];
    float4 bv = ((const float4*)b)[lane];
    float4 acc;
    acc.x = hv.x * w0 + bv.x;
    acc.y = hv.y * w0 + bv.y;
    acc.z = hv.z * w0 + bv.z;
    acc.w = hv.w * w0 + bv.w;

    int beg = ptr[node], endp = ptr[node + 1];
    int j = beg;
    for (; j + 3 < endp; j += 4) {
        int2 e0 = cedge[j],     e1 = cedge[j + 1];
        int2 e2 = cedge[j + 2], e3 = cedge[j + 3];
        float n0 = __int_as_float(e0.y), n1 = __int_as_float(e1.y);
        float n2 = __int_as_float(e2.y), n3 = __int_as_float(e3.y);
        float4 v0 = h4[(long)e0.x * 32 + lane];
        float4 v1 = h4[(long)e1.x * 32 + lane];
        float4 v2 = h4[(long)e2.x * 32 + lane];
        float4 v3 = h4[(long)e3.x * 32 + lane];
        acc.x += v0.x * n0; acc.y += v0.y * n0; acc.z += v0.z * n0; acc.w += v0.w * n0;
        acc.x += v1.x * n1; acc.y += v1.y * n1; acc.z += v1.z * n1; acc.w += v1.w * n1;
        acc.x += v2.x * n2; acc.y += v2.y * n2; acc.z += v2.z * n2; acc.w += v2.w * n2;
        acc.x += v3.x * n3; acc.y += v3.y * n3; acc.z += v3.z * n3; acc.w += v3.w * n3;
    }
    for (; j < endp; j++) {
        int2 e = cedge[j];
        float w = __int_as_float(e.y);
        float4 v = h4[(long)e.x * 32 + lane];
        acc.x += v.x * w; acc.y += v.y * w; acc.z += v.z * w; acc.w += v.w * w;
    }
    ((float4*)out)[(long)node * 32 + lane] = acc;
}

// ---------------------------------------------------------------------------
extern "C" void kernel_launch(void* const* d_in, const int* in_sizes, int n_in,
                              void* d_out, int out_size) {
    const float* x  = (const float*)d_in[0];
    const int*   ei = (const int*)  d_in[1];
    const float* W1 = (const float*)d_in[2];
    const float* b1 = (const float*)d_in[3];
    const float* W2 = (const float*)d_in[4];
    const float* b2 = (const float*)d_in[5];
    float* out = (float*)d_out;

    const int N = in_sizes[0] / DIM;
    const int E = in_sizes[1] / 2;
    const int* src = ei;
    const int* dst = ei + E;

    int *deg, *ptr, *cur, *bsum;
    int2* cedge;
    float *dinv, *h, *o1, *h2;
    uint32_t *w1h, *w1l, *w2h, *w2l;
    cudaGetSymbolAddress((void**)&deg,   g_deg);
    cudaGetSymbolAddress((void**)&dinv,  g_dinv);
    cudaGetSymbolAddress((void**)&ptr,   g_ptr);
    cudaGetSymbolAddress((void**)&cur,   g_cur);
    cudaGetSymbolAddress((void**)&bsum,  g_bsum);
    cudaGetSymbolAddress((void**)&cedge, g_cedge);
    cudaGetSymbolAddress((void**)&h,     g_h);
    cudaGetSymbolAddress((void**)&o1,    g_o1);
    cudaGetSymbolAddress((void**)&h2,    g_h2);
    cudaGetSymbolAddress((void**)&w1h,   g_w1h);
    cudaGetSymbolAddress((void**)&w1l,   g_w1l);
    cudaGetSymbolAddress((void**)&w2h,   g_w2h);
    cudaGetSymbolAddress((void**)&w2l,   g_w2l);

    const size_t smem_bytes = SM_U32 * sizeof(uint32_t);
    cudaFuncSetAttribute(k_gemm_mma<false>,
                         cudaFuncAttributeMaxDynamicSharedMemorySize, (int)smem_bytes);
    cudaFuncSetAttribute(k_gemm_mma<true>,
                         cudaFuncAttributeMaxDynamicSharedMemorySize, (int)smem_bytes);

    const int T = 256;
    const int nb_scan     = (N + SCAN_B - 1) / SCAN_B;
    const int gemm_blocks = (N + 127) / 128;

    cudaStream_t s2;
    cudaStreamCreateWithFlags(&s2, cudaStreamNonBlocking);
    cudaEvent_t e_fork, e_join;
    cudaEventCreateWithFlags(&e_fork, cudaEventDisableTiming);
    cudaEventCreateWithFlags(&e_join, cudaEventDisableTiming);

    // ---- fork: weight split + GEMM-1 on s2, CSR build on main ----
    cudaEventRecord(e_fork, 0);
    cudaStreamWaitEvent(s2, e_fork, 0);
    k_wsplit<<<(DIM * DIM / 2 + T - 1) / T, T, 0, s2>>>(W1, w1h, w1l);
    k_wsplit<<<(DIM * DIM / 2 + T - 1) / T, T, 0, s2>>>(W2, w2h, w2l);
    k_gemm_mma<false><<<gemm_blocks, 256, smem_bytes, s2>>>(x, w1h, w1l, h, N);
    cudaEventRecord(e_join, s2);

    cudaMemsetAsync(deg, 0, (size_t)N * sizeof(int));
    k_count<<<(E / 4 + T - 1) / T, T>>>(dst, deg, E);
    k_scan1<<<nb_scan, SCAN_B>>>(deg, ptr, bsum, dinv, N);
    k_scan3<<<(N + T - 1) / T, T>>>(ptr, bsum, cur, N, E, nb_scan);
    k_fill <<<(E / 4 + T - 1) / T, T>>>(src, dst, dinv, cur, cedge, E);

    // ---- join, then serial layer pipeline ----
    cudaStreamWaitEvent(0, e_join, 0);
    int ablk = (N * 32 + T - 1) / T;
    k_agg<<<ablk, T>>>(h, ptr, cedge, dinv, b1, o1, N);
    k_gemm_mma<true><<<gemm_blocks, 256, smem_bytes>>>(o1, w2h, w2l, h2, N);
    k_agg<<<ablk, T>>>(h2, ptr, cedge, dinv, b2, out, N);
}

// round 14
// speedup vs baseline: 1.3015x; 1.1492x over previous
#include <cuda_runtime.h>
#include <cuda_bf16.h>
#include <cstdint>

// ---------------------------------------------------------------------------
// GCN 2-layer forward on GB300.
// CSR pull-aggregation (packed int2 edges) + mma.sync bf16-split GEMM
// (3 passes HH+HL+LH, fp32 accum).
// GEMM v3: A fragments direct-from-global (in-register split) -> smem holds
// only the two B images (73.7KB) -> 2-3 CTAs/SM. B fragments are single
// LDS.64 via k-pair interleave; stride 72 u32 (== 8 mod 32) -> conflict-free.
// Schedule: [wsplit x2 + gemm1 on s2] || [CSR build on main]; join; serial
// agg1 -> gemm2 -> agg2.
// ---------------------------------------------------------------------------

#define MAX_N 50000
#define MAX_E 800000
#define DIM   128
#define SCAN_B 1024
#define AST 72                       // row stride in u32 (8 mod 32)
#define WIMG (DIM * AST)             // 9216 u32 per weight image

// scratch (device globals -- no allocation allowed)
__device__ int      g_deg  [MAX_N];
__device__ float    g_dinv [MAX_N];
__device__ int      g_ptr  [MAX_N + 1];
__device__ int      g_cur  [MAX_N];
__device__ int      g_bsum [64];
__device__ int2     g_cedge[MAX_E];
__device__ float    g_h    [MAX_N * DIM];
__device__ float    g_o1   [MAX_N * DIM];
__device__ float    g_h2   [MAX_N * DIM];
// pre-split, transposed, pair-packed, k-interleaved weights
__device__ uint32_t g_w1h[WIMG];
__device__ uint32_t g_w1l[WIMG];
__device__ uint32_t g_w2h[WIMG];
__device__ uint32_t g_w2l[WIMG];

// ---------------------------------------------------------------------------
__device__ __forceinline__ void bf16_split(float f, unsigned short& hi, unsigned short& lo) {
    __nv_bfloat16 h = __float2bfloat16(f);
    float fh = __bfloat162float(h);
    __nv_bfloat16 l = __float2bfloat16(f - fh);
    hi = __bfloat16_as_ushort(h);
    lo = __bfloat16_as_ushort(l);
}
__device__ __forceinline__ uint32_t pack2(unsigned short even_k, unsigned short odd_k) {
    return (uint32_t)even_k | ((uint32_t)odd_k << 16);
}
// split a float2 (consecutive k) into packed hi/lo u32
__device__ __forceinline__ void split2(float2 v, uint32_t& hi, uint32_t& lo) {
    unsigned short h0, l0, h1, l1;
    bf16_split(v.x, h0, l0);
    bf16_split(v.y, h1, l1);
    hi = pack2(h0, h1);
    lo = pack2(l0, l1);
}
__device__ __forceinline__ void mma16816(float* d, const uint32_t* a,
                                         uint32_t b0, uint32_t b1) {
    asm volatile(
        "mma.sync.aligned.m16n8k16.row.col.f32.bf16.bf16.f32 "
        "{%0,%1,%2,%3}, {%4,%5,%6,%7}, {%8,%9}, {%0,%1,%2,%3};"
        : "+f"(d[0]), "+f"(d[1]), "+f"(d[2]), "+f"(d[3])
        : "r"(a[0]), "r"(a[1]), "r"(a[2]), "r"(a[3]), "r"(b0), "r"(b1));
}

// ---------------------------------------------------------------------------
// weight prep: W[k][n] f32 -> [n][slot] packed bf16 pairs, stride AST.
// k-pair interleave within each group of 8: slot 2i <- k2 grp*8+i,
// slot 2i+1 <- k2 grp*8+i+4. One LDS.64 at (kb + 2*t4) yields (b0, b1).
__global__ void k_wsplit(const float* __restrict__ W,
                         uint32_t* __restrict__ Wh,
                         uint32_t* __restrict__ Wl) {
    int i = blockIdx.x * blockDim.x + threadIdx.x;
    if (i >= DIM * (DIM / 2)) return;
    int n = i >> 6, k2 = i & 63;
    int grp = k2 >> 3, ii = k2 & 7;
    int slot = grp * 8 + ((ii < 4) ? (2 * ii) : (2 * (ii - 4) + 1));
    float w0 = W[(2 * k2)     * DIM + n];
    float w1 = W[(2 * k2 + 1) * DIM + n];
    unsigned short h0, l0, h1, l1;
    bf16_split(w0, h0, l0);
    bf16_split(w1, h1, l1);
    Wh[n * AST + slot] = pack2(h0, h1);
    Wl[n * AST + slot] = pack2(l0, l1);
}

// ---------------------------------------------------------------------------
// GEMM v3 via mma.sync: C[128-tile,128] = A@W, bf16-split 3-pass.
// 256 thr = 8 warps in 4x2; warp tile m32 x n64. smem = B images only.
#define SMB_H 0
#define SMB_L WIMG
#define SM_U32 (2 * WIMG)            // 18432 u32 = 73728 B

template <bool RELU>
__global__ __launch_bounds__(256) void k_gemm_mma(const float* __restrict__ A,
                                                  const uint32_t* __restrict__ Bh,
                                                  const uint32_t* __restrict__ Bl,
                                                  float* __restrict__ C, int M) {
    extern __shared__ uint32_t sm[];
    const int tid  = threadIdx.x;
    const int m0   = blockIdx.x * 128;
    const int w    = tid >> 5;
    const int lane = tid & 31;
    const int g    = lane >> 2;     // 0..7
    const int t4   = lane & 3;      // 0..3
    const int wm   = w & 3;         // 4 row-blocks of 32
    const int wn   = w >> 2;        // 2 col-blocks of 64

    // --- stage B (pre-packed, pre-interleaved): linear float4 copy ---
    for (int i = tid; i < WIMG / 4; i += 256) {
        ((float4*)(sm + SMB_H))[i] = ((const float4*)Bh)[i];
        ((float4*)(sm + SMB_L))[i] = ((const float4*)Bl)[i];
    }
    __syncthreads();

    float acc[2][8][4];
#pragma unroll
    for (int mt = 0; mt < 2; mt++)
#pragma unroll
        for (int nt = 0; nt < 8; nt++)
#pragma unroll
            for (int q = 0; q < 4; q++) acc[mt][nt][q] = 0.f;

#pragma unroll
    for (int ks = 0; ks < 8; ks++) {
        const int kb = ks * 8;              // slot base
        const int c0 = ks * 16 + 2 * t4;    // f32 col of k-pair t4

        // --- A fragments straight from global, split in registers ---
        uint32_t ah[2][4], al[2][4];
#pragma unroll
        for (int mt = 0; mt < 2; mt++) {
            int r  = m0 + wm * 32 + mt * 16 + g;
            int r8 = r + 8;
            float2 x00 = make_float2(0.f, 0.f), x01 = x00, x10 = x00, x11 = x00;
            if (r < M) {
                const float* Ar = A + (long)r * DIM;
                x00 = *(const float2*)(Ar + c0);
                x01 = *(const float2*)(Ar + c0 + 8);
            }
            if (r8 < M) {
                const float* Ar8 = A + (long)r8 * DIM;
                x10 = *(const float2*)(Ar8 + c0);
                x11 = *(const float2*)(Ar8 + c0 + 8);
            }
            if (RELU) {
                x00.x = fmaxf(x00.x, 0.f); x00.y = fmaxf(x00.y, 0.f);
                x01.x = fmaxf(x01.x, 0.f); x01.y = fmaxf(x01.y, 0.f);
                x10.x = fmaxf(x10.x, 0.f); x10.y = fmaxf(x10.y, 0.f);
                x11.x = fmaxf(x11.x, 0.f); x11.y = fmaxf(x11.y, 0.f);
            }
            split2(x00, ah[mt][0], al[mt][0]);   // row r,  k-pair t4
            split2(x10, ah[mt][1], al[mt][1]);   // row r+8, k-pair t4
            split2(x01, ah[mt][2], al[mt][2]);   // row r,  k-pair t4+4
            split2(x11, ah[mt][3], al[mt][3]);   // row r+8, k-pair t4+4
        }

#pragma unroll
        for (int nt = 0; nt < 8; nt++) {
            int n  = wn * 64 + nt * 8 + g;
            int bi = n * AST + kb + 2 * t4;      // LDS.64, conflict-free
            uint2 bh = *(const uint2*)(sm + SMB_H + bi);
            uint2 bl = *(const uint2*)(sm + SMB_L + bi);
#pragma unroll
            for (int mt = 0; mt < 2; mt++) {
                mma16816(acc[mt][nt], ah[mt], bh.x, bh.y);   // HH
                mma16816(acc[mt][nt], ah[mt], bl.x, bl.y);   // HL
                mma16816(acc[mt][nt], al[mt], bh.x, bh.y);   // LH
            }
        }
    }

    // epilogue
#pragma unroll
    for (int mt = 0; mt < 2; mt++) {
        int r0 = m0 + wm * 32 + mt * 16 + g;
        int r1 = r0 + 8;
#pragma unroll
        for (int nt = 0; nt < 8; nt++) {
            int col = wn * 64 + nt * 8 + 2 * t4;
            if (r0 < M)
                *(float2*)(C + (long)r0 * DIM + col) =
                    make_float2(acc[mt][nt][0], acc[mt][nt][1]);
            if (r1 < M)
                *(float2*)(C + (long)r1 * DIM + col) =
                    make_float2(acc[mt][nt][2], acc[mt][nt][3]);
        }
    }
}

// ---------------------------------------------------------------------------
// CSR build
__global__ void k_count(const int* __restrict__ dst, int* deg, int E) {
    int base = (blockIdx.x * blockDim.x + threadIdx.x) * 4;
    if (base + 3 < E) {
        int4 d4 = *(const int4*)(dst + base);
        atomicAdd(&deg[d4.x], 1);
        atomicAdd(&deg[d4.y], 1);
        atomicAdd(&deg[d4.z], 1);
        atomicAdd(&deg[d4.w], 1);
    } else {
        for (int e = base; e < E; e++) atomicAdd(&deg[dst[e]], 1);
    }
}

__global__ __launch_bounds__(SCAN_B) void k_scan1(const int* __restrict__ deg,
                                                  int* ptr, int* bsum,
                                                  float* dinv, int n) {
    __shared__ int ws[32];
    int t = threadIdx.x;
    int lane = t & 31, w = t >> 5;
    int i = blockIdx.x * SCAN_B + t;
    int v = (i < n) ? deg[i] : 0;
    if (i < n) dinv[i] = rsqrtf((float)(v + 1));
    int x = v;
#pragma unroll
    for (int off = 1; off < 32; off <<= 1) {
        int y = __shfl_up_sync(0xFFFFFFFFu, x, off);
        if (lane >= off) x += y;
    }
    if (lane == 31) ws[w] = x;
    __syncthreads();
    if (w == 0) {
        int s = ws[lane];
#pragma unroll
        for (int off = 1; off < 32; off <<= 1) {
            int y = __shfl_up_sync(0xFFFFFFFFu, s, off);
            if (lane >= off) s += y;
        }
        ws[lane] = s;
    }
    __syncthreads();
    int incl = x + ((w > 0) ? ws[w - 1] : 0);
    if (i < n) ptr[i] = incl - v;
    if (t == SCAN_B - 1) bsum[blockIdx.x] = incl;
}

__global__ void k_scan3(int* ptr, const int* __restrict__ bsum, int* cur,
                        int n, int E, int nb) {
    __shared__ int sb_[64];
    int t = threadIdx.x;
    if (t < 64) sb_[t] = (t < nb) ? bsum[t] : 0;
    __syncthreads();
#pragma unroll
    for (int off = 1; off < 64; off <<= 1) {
        int x = (t < 64 && t >= off) ? sb_[t - off] : 0;
        __syncthreads();
        if (t < 64) sb_[t] += x;
        __syncthreads();
    }
    int i = blockIdx.x * blockDim.x + t;
    if (i < n) {
        int blk = i / SCAN_B;
        int pre = (blk > 0) ? sb_[blk - 1] : 0;
        int p = ptr[i] + pre;
        ptr[i] = p;
        cur[i] = p;
    }
    if (i == 0) ptr[n] = E;
}

__global__ void k_fill(const int* __restrict__ src, const int* __restrict__ dst,
                       const float* __restrict__ dinv, int* cur,
                       int2* cedge, int E) {
    int base = (blockIdx.x * blockDim.x + threadIdx.x) * 4;
    if (base + 3 < E) {
        int4 s4 = *(const int4*)(src + base);
        int4 d4 = *(const int4*)(dst + base);
        float ns0 = dinv[s4.x], ns1 = dinv[s4.y], ns2 = dinv[s4.z], ns3 = dinv[s4.w];
        float nd0 = dinv[d4.x], nd1 = dinv[d4.y], nd2 = dinv[d4.z], nd3 = dinv[d4.w];
        int p0 = atomicAdd(&cur[d4.x], 1);
        int p1 = atomicAdd(&cur[d4.y], 1);
        int p2 = atomicAdd(&cur[d4.z], 1);
        int p3 = atomicAdd(&cur[d4.w], 1);
        cedge[p0] = make_int2(s4.x, __float_as_int(ns0 * nd0));
        cedge[p1] = make_int2(s4.y, __float_as_int(ns1 * nd1));
        cedge[p2] = make_int2(s4.z, __float_as_int(ns2 * nd2));
        cedge[p3] = make_int2(s4.w, __float_as_int(ns3 * nd3));
    } else {
        for (int e = base; e < E; e++) {
            int s = src[e], d = dst[e];
            int pos = atomicAdd(&cur[d], 1);
            cedge[pos] = make_int2(s, __float_as_int(dinv[s] * dinv[d]));
        }
    }
}

// ---------------------------------------------------------------------------
// pull-aggregation: warp per node, packed int2 edges.
__global__ __launch_bounds__(256) void k_agg(const float* __restrict__ h,
                                             const int* __restrict__ ptr,
                                             const int2* __restrict__ cedge,
                                             const float* __restrict__ dinv,
                                             const float* __restrict__ b,
                                             float* __restrict__ out, int n) {
    int node = (blockIdx.x * blockDim.x + threadIdx.x) >> 5;
    int lane = threadIdx.x & 31;
    if (node >= n) return;

    const float4* h4 = (const float4*)h;
    float di = dinv[node];
    float w0 = di * di;
    float4 hv = h4[(long)node * 32 + lane];
    float4 bv = ((const float4*)b)[lane];
    float4 acc;
    acc.x = hv.x * w0 + bv.x;
    acc.y = hv.y * w0 + bv.y;
    acc.z = hv.z * w0 + bv.z;
    acc.w = hv.w * w0 + bv.w;

    int beg = ptr[node], endp = ptr[node + 1];
    int j = beg;
    for (; j + 3 < endp; j += 4) {
        int2 e0 = cedge[j],     e1 = cedge[j + 1];
        int2 e2 = cedge[j + 2], e3 = cedge[j + 3];
        float n0 = __int_as_float(e0.y), n1 = __int_as_float(e1.y);
        float n2 = __int_as_float(e2.y), n3 = __int_as_float(e3.y);
        float4 v0 = h4[(long)e0.x * 32 + lane];
        float4 v1 = h4[(long)e1.x * 32 + lane];
        float4 v2 = h4[(long)e2.x * 32 + lane];
        float4 v3 = h4[(long)e3.x * 32 + lane];
        acc.x += v0.x * n0; acc.y += v0.y * n0; acc.z += v0.z * n0; acc.w += v0.w * n0;
        acc.x += v1.x * n1; acc.y += v1.y * n1; acc.z += v1.z * n1; acc.w += v1.w * n1;
        acc.x += v2.x * n2; acc.y += v2.y * n2; acc.z += v2.z * n2; acc.w += v2.w * n2;
        acc.x += v3.x * n3; acc.y += v3.y * n3; acc.z += v3.z * n3; acc.w += v3.w * n3;
    }
    for (; j < endp; j++) {
        int2 e = cedge[j];
        float w = __int_as_float(e.y);
        float4 v = h4[(long)e.x * 32 + lane];
        acc.x += v.x * w; acc.y += v.y * w; acc.z += v.z * w; acc.w += v.w * w;
    }
    ((float4*)out)[(long)node * 32 + lane] = acc;
}

// ---------------------------------------------------------------------------
extern "C" void kernel_launch(void* const* d_in, const int* in_sizes, int n_in,
                              void* d_out, int out_size) {
    const float* x  = (const float*)d_in[0];
    const int*   ei = (const int*)  d_in[1];
    const float* W1 = (const float*)d_in[2];
    const float* b1 = (const float*)d_in[3];
    const float* W2 = (const float*)d_in[4];
    const float* b2 = (const float*)d_in[5];
    float* out = (float*)d_out;

    const int N = in_sizes[0] / DIM;
    const int E = in_sizes[1] / 2;
    const int* src = ei;
    const int* dst = ei + E;

    int *deg, *ptr, *cur, *bsum;
    int2* cedge;
    float *dinv, *h, *o1, *h2;
    uint32_t *w1h, *w1l, *w2h, *w2l;
    cudaGetSymbolAddress((void**)&deg,   g_deg);
    cudaGetSymbolAddress((void**)&dinv,  g_dinv);
    cudaGetSymbolAddress((void**)&ptr,   g_ptr);
    cudaGetSymbolAddress((void**)&cur,   g_cur);
    cudaGetSymbolAddress((void**)&bsum,  g_bsum);
    cudaGetSymbolAddress((void**)&cedge, g_cedge);
    cudaGetSymbolAddress((void**)&h,     g_h);
    cudaGetSymbolAddress((void**)&o1,    g_o1);
    cudaGetSymbolAddress((void**)&h2,    g_h2);
    cudaGetSymbolAddress((void**)&w1h,   g_w1h);
    cudaGetSymbolAddress((void**)&w1l,   g_w1l);
    cudaGetSymbolAddress((void**)&w2h,   g_w2h);
    cudaGetSymbolAddress((void**)&w2l,   g_w2l);

    const size_t smem_bytes = SM_U32 * sizeof(uint32_t);
    cudaFuncSetAttribute(k_gemm_mma<false>,
                         cudaFuncAttributeMaxDynamicSharedMemorySize, (int)smem_bytes);
    cudaFuncSetAttribute(k_gemm_mma<true>,
                         cudaFuncAttributeMaxDynamicSharedMemorySize, (int)smem_bytes);

    const int T = 256;
    const int nb_scan     = (N + SCAN_B - 1) / SCAN_B;
    const int gemm_blocks = (N + 127) / 128;

    cudaStream_t s2;
    cudaStreamCreateWithFlags(&s2, cudaStreamNonBlocking);
    cudaEvent_t e_fork, e_join;
    cudaEventCreateWithFlags(&e_fork, cudaEventDisableTiming);
    cudaEventCreateWithFlags(&e_join, cudaEventDisableTiming);

    // ---- fork: weight split + GEMM-1 on s2, CSR build on main ----
    cudaEventRecord(e_fork, 0);
    cudaStreamWaitEvent(s2, e_fork, 0);
    k_wsplit<<<(DIM * DIM / 2 + T - 1) / T, T, 0, s2>>>(W1, w1h, w1l);
    k_wsplit<<<(DIM * DIM / 2 + T - 1) / T, T, 0, s2>>>(W2, w2h, w2l);
    k_gemm_mma<false><<<gemm_blocks, 256, smem_bytes, s2>>>(x, w1h, w1l, h, N);
    cudaEventRecord(e_join, s2);

    cudaMemsetAsync(deg, 0, (size_t)N * sizeof(int));
    k_count<<<(E / 4 + T - 1) / T, T>>>(dst, deg, E);
    k_scan1<<<nb_scan, SCAN_B>>>(deg, ptr, bsum, dinv, N);
    k_scan3<<<(N + T - 1) / T, T>>>(ptr, bsum, cur, N, E, nb_scan);
    k_fill <<<(E / 4 + T - 1) / T, T>>>(src, dst, dinv, cur, cedge, E);

    // ---- join, then serial layer pipeline ----
    cudaStreamWaitEvent(0, e_join, 0);
    int ablk = (N * 32 + T - 1) / T;
    k_agg<<<ablk, T>>>(h, ptr, cedge, dinv, b1, o1, N);
    k_gemm_mma<true><<<gemm_blocks, 256, smem_bytes>>>(o1, w2h, w2l, h2, N);
    k_agg<<<ablk, T>>>(h2, ptr, cedge, dinv, b2, out, N);
}

// round 16
// speedup vs baseline: 1.4105x; 1.0838x over previous
#include <cuda_runtime.h>
#include <cuda_bf16.h>
#include <cstdint>

// ---------------------------------------------------------------------------
// GCN 2-layer forward on GB300.
// CSR pull-aggregation (packed int2 edges) + mma.sync bf16-split GEMM
// (3 passes HH+HL+LH, fp32 accum).
// GEMM v4: A direct-from-global with FAST in-register split:
//   hi-pair = 1x PRMT(0x7632) (truncation), lo-pair = AND/FSUB + cvt.rn.bf16x2.
// smem holds only B images (73.7KB) -> 2 CTAs/SM; B frags = LDS.64,
// stride 72 u32 (== 8 mod 32) -> conflict-free.
// Schedule: [wsplit x2 + gemm1 on s2] || [CSR build on main]; join; serial
// agg1 -> gemm2 -> agg2.
// ---------------------------------------------------------------------------

#define MAX_N 50000
#define MAX_E 800000
#define DIM   128
#define SCAN_B 1024
#define AST 72                       // row stride in u32 (8 mod 32)
#define WIMG (DIM * AST)             // 9216 u32 per weight image

// scratch (device globals -- no allocation allowed)
__device__ int      g_deg  [MAX_N];
__device__ float    g_dinv [MAX_N];
__device__ int      g_ptr  [MAX_N + 1];
__device__ int      g_cur  [MAX_N];
__device__ int      g_bsum [64];
__device__ int2     g_cedge[MAX_E];
__device__ float    g_h    [MAX_N * DIM];
__device__ float    g_o1   [MAX_N * DIM];
__device__ float    g_h2   [MAX_N * DIM];
// pre-split, transposed, pair-packed, k-interleaved weights
__device__ uint32_t g_w1h[WIMG];
__device__ uint32_t g_w1l[WIMG];
__device__ uint32_t g_w2h[WIMG];
__device__ uint32_t g_w2l[WIMG];

// ---------------------------------------------------------------------------
__device__ __forceinline__ void bf16_split(float f, unsigned short& hi, unsigned short& lo) {
    __nv_bfloat16 h = __float2bfloat16(f);
    float fh = __bfloat162float(h);
    __nv_bfloat16 l = __float2bfloat16(f - fh);
    hi = __bfloat16_as_ushort(h);
    lo = __bfloat16_as_ushort(l);
}
__device__ __forceinline__ uint32_t pack2(unsigned short even_k, unsigned short odd_k) {
    return (uint32_t)even_k | ((uint32_t)odd_k << 16);
}
// FAST split of float2 (consecutive k) into packed hi/lo u32.
// hi = truncated top-16 bits (PRMT), lo = bf16(round(v - trunc(v))).
__device__ __forceinline__ void split2_fast(float2 v, uint32_t& hi, uint32_t& lo) {
    uint32_t u0 = __float_as_uint(v.x), u1 = __float_as_uint(v.y);
    uint32_t h;
    asm("prmt.b32 %0, %1, %2, 0x7632;" : "=r"(h) : "r"(u0), "r"(u1));
    float f0h = __uint_as_float(u0 & 0xFFFF0000u);
    float f1h = __uint_as_float(u1 & 0xFFFF0000u);
    float r0 = v.x - f0h, r1 = v.y - f1h;
    uint32_t l;
    asm("cvt.rn.bf16x2.f32 %0, %1, %2;" : "=r"(l) : "f"(r1), "f"(r0));
    hi = h; lo = l;
}
__device__ __forceinline__ void mma16816(float* d, const uint32_t* a,
                                         uint32_t b0, uint32_t b1) {
    asm volatile(
        "mma.sync.aligned.m16n8k16.row.col.f32.bf16.bf16.f32 "
        "{%0,%1,%2,%3}, {%4,%5,%6,%7}, {%8,%9}, {%0,%1,%2,%3};"
        : "+f"(d[0]), "+f"(d[1]), "+f"(d[2]), "+f"(d[3])
        : "r"(a[0]), "r"(a[1]), "r"(a[2]), "r"(a[3]), "r"(b0), "r"(b1));
}

// ---------------------------------------------------------------------------
// weight prep: W[k][n] f32 -> [n][slot] packed bf16 pairs, stride AST.
// k-pair interleave within each group of 8: slot 2i <- k2 grp*8+i,
// slot 2i+1 <- k2 grp*8+i+4. One LDS.64 at (kb + 2*t4) yields (b0, b1).
__global__ void k_wsplit(const float* __restrict__ W,
                         uint32_t* __restrict__ Wh,
                         uint32_t* __restrict__ Wl) {
    int i = blockIdx.x * blockDim.x + threadIdx.x;
    if (i >= DIM * (DIM / 2)) return;
    int n = i >> 6, k2 = i & 63;
    int grp = k2 >> 3, ii = k2 & 7;
    int slot = grp * 8 + ((ii < 4) ? (2 * ii) : (2 * (ii - 4) + 1));
    float w0 = W[(2 * k2)     * DIM + n];
    float w1 = W[(2 * k2 + 1) * DIM + n];
    unsigned short h0, l0, h1, l1;
    bf16_split(w0, h0, l0);
    bf16_split(w1, h1, l1);
    Wh[n * AST + slot] = pack2(h0, h1);
    Wl[n * AST + slot] = pack2(l0, l1);
}

// ---------------------------------------------------------------------------
// GEMM v4 via mma.sync: C[128-tile,128] = A@W, bf16-split 3-pass.
// 256 thr = 8 warps in 4x2; warp tile m32 x n64. smem = B images only.
#define SMB_H 0
#define SMB_L WIMG
#define SM_U32 (2 * WIMG)            // 18432 u32 = 73728 B

template <bool RELU>
__global__ __launch_bounds__(256) void k_gemm_mma(const float* __restrict__ A,
                                                  const uint32_t* __restrict__ Bh,
                                                  const uint32_t* __restrict__ Bl,
                                                  float* __restrict__ C, int M) {
    extern __shared__ uint32_t sm[];
    const int tid  = threadIdx.x;
    const int m0   = blockIdx.x * 128;
    const int w    = tid >> 5;
    const int lane = tid & 31;
    const int g    = lane >> 2;     // 0..7
    const int t4   = lane & 3;      // 0..3
    const int wm   = w & 3;         // 4 row-blocks of 32
    const int wn   = w >> 2;        // 2 col-blocks of 64

    // --- stage B (pre-packed, pre-interleaved): linear float4 copy ---
    for (int i = tid; i < WIMG / 4; i += 256) {
        ((float4*)(sm + SMB_H))[i] = ((const float4*)Bh)[i];
        ((float4*)(sm + SMB_L))[i] = ((const float4*)Bl)[i];
    }
    __syncthreads();

    float acc[2][8][4];
#pragma unroll
    for (int mt = 0; mt < 2; mt++)
#pragma unroll
        for (int nt = 0; nt < 8; nt++)
#pragma unroll
            for (int q = 0; q < 4; q++) acc[mt][nt][q] = 0.f;

#pragma unroll
    for (int ks = 0; ks < 8; ks++) {
        const int kb = ks * 8;              // slot base
        const int c0 = ks * 16 + 2 * t4;    // f32 col of k-pair t4

        // --- A fragments straight from global, fast split in registers ---
        uint32_t ah[2][4], al[2][4];
#pragma unroll
        for (int mt = 0; mt < 2; mt++) {
            int r  = m0 + wm * 32 + mt * 16 + g;
            int r8 = r + 8;
            float2 x00 = make_float2(0.f, 0.f), x01 = x00, x10 = x00, x11 = x00;
            if (r < M) {
                const float* Ar = A + (long)r * DIM;
                x00 = *(const float2*)(Ar + c0);
                x01 = *(const float2*)(Ar + c0 + 8);
            }
            if (r8 < M) {
                const float* Ar8 = A + (long)r8 * DIM;
                x10 = *(const float2*)(Ar8 + c0);
                x11 = *(const float2*)(Ar8 + c0 + 8);
            }
            if (RELU) {
                x00.x = fmaxf(x00.x, 0.f); x00.y = fmaxf(x00.y, 0.f);
                x01.x = fmaxf(x01.x, 0.f); x01.y = fmaxf(x01.y, 0.f);
                x10.x = fmaxf(x10.x, 0.f); x10.y = fmaxf(x10.y, 0.f);
                x11.x = fmaxf(x11.x, 0.f); x11.y = fmaxf(x11.y, 0.f);
            }
            split2_fast(x00, ah[mt][0], al[mt][0]);   // row r,  k-pair t4
            split2_fast(x10, ah[mt][1], al[mt][1]);   // row r+8, k-pair t4
            split2_fast(x01, ah[mt][2], al[mt][2]);   // row r,  k-pair t4+4
            split2_fast(x11, ah[mt][3], al[mt][3]);   // row r+8, k-pair t4+4
        }

#pragma unroll
        for (int nt = 0; nt < 8; nt++) {
            int n  = wn * 64 + nt * 8 + g;
            int bi = n * AST + kb + 2 * t4;      // LDS.64, conflict-free
            uint2 bh = *(const uint2*)(sm + SMB_H + bi);
            uint2 bl = *(const uint2*)(sm + SMB_L + bi);
#pragma unroll
            for (int mt = 0; mt < 2; mt++) {
                mma16816(acc[mt][nt], ah[mt], bh.x, bh.y);   // HH
                mma16816(acc[mt][nt], ah[mt], bl.x, bl.y);   // HL
                mma16816(acc[mt][nt], al[mt], bh.x, bh.y);   // LH
            }
        }
    }

    // epilogue
#pragma unroll
    for (int mt = 0; mt < 2; mt++) {
        int r0 = m0 + wm * 32 + mt * 16 + g;
        int r1 = r0 + 8;
#pragma unroll
        for (int nt = 0; nt < 8; nt++) {
            int col = wn * 64 + nt * 8 + 2 * t4;
            if (r0 < M)
                *(float2*)(C + (long)r0 * DIM + col) =
                    make_float2(acc[mt][nt][0], acc[mt][nt][1]);
            if (r1 < M)
                *(float2*)(C + (long)r1 * DIM + col) =
                    make_float2(acc[mt][nt][2], acc[mt][nt][3]);
        }
    }
}

// ---------------------------------------------------------------------------
// CSR build
__global__ void k_count(const int* __restrict__ dst, int* deg, int E) {
    int base = (blockIdx.x * blockDim.x + threadIdx.x) * 4;
    if (base + 3 < E) {
        int4 d4 = *(const int4*)(dst + base);
        atomicAdd(&deg[d4.x], 1);
        atomicAdd(&deg[d4.y], 1);
        atomicAdd(&deg[d4.z], 1);
        atomicAdd(&deg[d4.w], 1);
    } else {
        for (int e = base; e < E; e++) atomicAdd(&deg[dst[e]], 1);
    }
}

__global__ __launch_bounds__(SCAN_B) void k_scan1(const int* __restrict__ deg,
                                                  int* ptr, int* bsum,
                                                  float* dinv, int n) {
    __shared__ int ws[32];
    int t = threadIdx.x;
    int lane = t & 31, w = t >> 5;
    int i = blockIdx.x * SCAN_B + t;
    int v = (i < n) ? deg[i] : 0;
    if (i < n) dinv[i] = rsqrtf((float)(v + 1));
    int x = v;
#pragma unroll
    for (int off = 1; off < 32; off <<= 1) {
        int y = __shfl_up_sync(0xFFFFFFFFu, x, off);
        if (lane >= off) x += y;
    }
    if (lane == 31) ws[w] = x;
    __syncthreads();
    if (w == 0) {
        int s = ws[lane];
#pragma unroll
        for (int off = 1; off < 32; off <<= 1) {
            int y = __shfl_up_sync(0xFFFFFFFFu, s, off);
            if (lane >= off) s += y;
        }
        ws[lane] = s;
    }
    __syncthreads();
    int incl = x + ((w > 0) ? ws[w - 1] : 0);
    if (i < n) ptr[i] = incl - v;
    if (t == SCAN_B - 1) bsum[blockIdx.x] = incl;
}

__global__ void k_scan3(int* ptr, const int* __restrict__ bsum, int* cur,
                        int n, int E, int nb) {
    __shared__ int sb_[64];
    int t = threadIdx.x;
    if (t < 64) sb_[t] = (t < nb) ? bsum[t] : 0;
    __syncthreads();
#pragma unroll
    for (int off = 1; off < 64; off <<= 1) {
        int x = (t < 64 && t >= off) ? sb_[t - off] : 0;
        __syncthreads();
        if (t < 64) sb_[t] += x;
        __syncthreads();
    }
    int i = blockIdx.x * blockDim.x + t;
    if (i < n) {
        int blk = i / SCAN_B;
        int pre = (blk > 0) ? sb_[blk - 1] : 0;
        int p = ptr[i] + pre;
        ptr[i] = p;
        cur[i] = p;
    }
    if (i == 0) ptr[n] = E;
}

__global__ void k_fill(const int* __restrict__ src, const int* __restrict__ dst,
                       const float* __restrict__ dinv, int* cur,
                       int2* cedge, int E) {
    int base = (blockIdx.x * blockDim.x + threadIdx.x) * 4;
    if (base + 3 < E) {
        int4 s4 = *(const int4*)(src + base);
        int4 d4 = *(const int4*)(dst + base);
        float ns0 = dinv[s4.x], ns1 = dinv[s4.y], ns2 = dinv[s4.z], ns3 = dinv[s4.w];
        float nd0 = dinv[d4.x], nd1 = dinv[d4.y], nd2 = dinv[d4.z], nd3 = dinv[d4.w];
        int p0 = atomicAdd(&cur[d4.x], 1);
        int p1 = atomicAdd(&cur[d4.y], 1);
        int p2 = atomicAdd(&cur[d4.z], 1);
        int p3 = atomicAdd(&cur[d4.w], 1);
        cedge[p0] = make_int2(s4.x, __float_as_int(ns0 * nd0));
        cedge[p1] = make_int2(s4.y, __float_as_int(ns1 * nd1));
        cedge[p2] = make_int2(s4.z, __float_as_int(ns2 * nd2));
        cedge[p3] = make_int2(s4.w, __float_as_int(ns3 * nd3));
    } else {
        for (int e = base; e < E; e++) {
            int s = src[e], d = dst[e];
            int pos = atomicAdd(&cur[d], 1);
            cedge[pos] = make_int2(s, __float_as_int(dinv[s] * dinv[d]));
        }
    }
}

// ---------------------------------------------------------------------------
// pull-aggregation: warp per node, packed int2 edges.
__global__ __launch_bounds__(256) void k_agg(const float* __restrict__ h,
                                             const int* __restrict__ ptr,
                                             const int2* __restrict__ cedge,
                                             const float* __restrict__ dinv,
                                             const float* __restrict__ b,
                                             float* __restrict__ out, int n) {
    int node = (blockIdx.x * blockDim.x + threadIdx.x) >> 5;
    int lane = threadIdx.x & 31;
    if (node >= n) return;

    const float4* h4 = (const float4*)h;
    float di = dinv[node];
    float w0 = di * di;
    float4 hv = h4[(long)node * 32 + lane];
    float4 bv = ((const float4*)b)[lane];
    float4 acc;
    acc.x = hv.x * w0 + bv.x;
    acc.y = hv.y * w0 + bv.y;
    acc.z = hv.z * w0 + bv.z;
    acc.w = hv.w * w0 + bv.w;

    int beg = ptr[node], endp = ptr[node + 1];
    int j = beg;
    for (; j + 3 < endp; j += 4) {
        int2 e0 = cedge[j],     e1 = cedge[j + 1];
        int2 e2 = cedge[j + 2], e3 = cedge[j + 3];
        float n0 = __int_as_float(e0.y), n1 = __int_as_float(e1.y);
        float n2 = __int_as_float(e2.y), n3 = __int_as_float(e3.y);
        float4 v0 = h4[(long)e0.x * 32 + lane];
        float4 v1 = h4[(long)e1.x * 32 + lane];
        float4 v2 = h4[(long)e2.x * 32 + lane];
        float4 v3 = h4[(long)e3.x * 32 + lane];
        acc.x += v0.x * n0; acc.y += v0.y * n0; acc.z += v0.z * n0; acc.w += v0.w * n0;
        acc.x += v1.x * n1; acc.y += v1.y * n1; acc.z += v1.z * n1; acc.w += v1.w * n1;
        acc.x += v2.x * n2; acc.y += v2.y * n2; acc.z += v2.z * n2; acc.w += v2.w * n2;
        acc.x += v3.x * n3; acc.y += v3.y * n3; acc.z += v3.z * n3; acc.w += v3.w * n3;
    }
    for (; j < endp; j++) {
        int2 e = cedge[j];
        float w = __int_as_float(e.y);
        float4 v = h4[(long)e.x * 32 + lane];
        acc.x += v.x * w; acc.y += v.y * w; acc.z += v.z * w; acc.w += v.w * w;
    }
    ((float4*)out)[(long)node * 32 + lane] = acc;
}

// ---------------------------------------------------------------------------
extern "C" void kernel_launch(void* const* d_in, const int* in_sizes, int n_in,
                              void* d_out, int out_size) {
    const float* x  = (const float*)d_in[0];
    const int*   ei = (const int*)  d_in[1];
    const float* W1 = (const float*)d_in[2];
    const float* b1 = (const float*)d_in[3];
    const float* W2 = (const float*)d_in[4];
    const float* b2 = (const float*)d_in[5];
    float* out = (float*)d_out;

    const int N = in_sizes[0] / DIM;
    const int E = in_sizes[1] / 2;
    const int* src = ei;
    const int* dst = ei + E;

    int *deg, *ptr, *cur, *bsum;
    int2* cedge;
    float *dinv, *h, *o1, *h2;
    uint32_t *w1h, *w1l, *w2h, *w2l;
    cudaGetSymbolAddress((void**)&deg,   g_deg);
    cudaGetSymbolAddress((void**)&dinv,  g_dinv);
    cudaGetSymbolAddress((void**)&ptr,   g_ptr);
    cudaGetSymbolAddress((void**)&cur,   g_cur);
    cudaGetSymbolAddress((void**)&bsum,  g_bsum);
    cudaGetSymbolAddress((void**)&cedge, g_cedge);
    cudaGetSymbolAddress((void**)&h,     g_h);
    cudaGetSymbolAddress((void**)&o1,    g_o1);
    cudaGetSymbolAddress((void**)&h2,    g_h2);
    cudaGetSymbolAddress((void**)&w1h,   g_w1h);
    cudaGetSymbolAddress((void**)&w1l,   g_w1l);
    cudaGetSymbolAddress((void**)&w2h,   g_w2h);
    cudaGetSymbolAddress((void**)&w2l,   g_w2l);

    const size_t smem_bytes = SM_U32 * sizeof(uint32_t);
    cudaFuncSetAttribute(k_gemm_mma<false>,
                         cudaFuncAttributeMaxDynamicSharedMemorySize, (int)smem_bytes);
    cudaFuncSetAttribute(k_gemm_mma<true>,
                         cudaFuncAttributeMaxDynamicSharedMemorySize, (int)smem_bytes);

    const int T = 256;
    const int nb_scan     = (N + SCAN_B - 1) / SCAN_B;
    const int gemm_blocks = (N + 127) / 128;

    cudaStream_t s2;
    cudaStreamCreateWithFlags(&s2, cudaStreamNonBlocking);
    cudaEvent_t e_fork, e_join;
    cudaEventCreateWithFlags(&e_fork, cudaEventDisableTiming);
    cudaEventCreateWithFlags(&e_join, cudaEventDisableTiming);

    // ---- fork: weight split + GEMM-1 on s2, CSR build on main ----
    cudaEventRecord(e_fork, 0);
    cudaStreamWaitEvent(s2, e_fork, 0);
    k_wsplit<<<(DIM * DIM / 2 + T - 1) / T, T, 0, s2>>>(W1, w1h, w1l);
    k_wsplit<<<(DIM * DIM / 2 + T - 1) / T, T, 0, s2>>>(W2, w2h, w2l);
    k_gemm_mma<false><<<gemm_blocks, 256, smem_bytes, s2>>>(x, w1h, w1l, h, N);
    cudaEventRecord(e_join, s2);

    cudaMemsetAsync(deg, 0, (size_t)N * sizeof(int));
    k_count<<<(E / 4 + T - 1) / T, T>>>(dst, deg, E);
    k_scan1<<<nb_scan, SCAN_B>>>(deg, ptr, bsum, dinv, N);
    k_scan3<<<(N + T - 1) / T, T>>>(ptr, bsum, cur, N, E, nb_scan);
    k_fill <<<(E / 4 + T - 1) / T, T>>>(src, dst, dinv, cur, cedge, E);

    // ---- join, then serial layer pipeline ----
    cudaStreamWaitEvent(0, e_join, 0);
    int ablk = (N * 32 + T - 1) / T;
    k_agg<<<ablk, T>>>(h, ptr, cedge, dinv, b1, o1, N);
    k_gemm_mma<true><<<gemm_blocks, 256, smem_bytes>>>(o1, w2h, w2l, h2, N);
    k_agg<<<ablk, T>>>(h2, ptr, cedge, dinv, b2, out, N);
}